// round 13
// baseline (speedup 1.0000x reference)
#include <cuda_runtime.h>
#include <cuda_fp16.h>
#include <cstdint>

#define N_NODES 100000
#define N_EDGES 3200000
#define IN_DIM  256
#define EPS     1e-5f

// ---------------- scratch (__device__ globals; no allocations) ----------------
__device__ __align__(16) __half g_xh  [(size_t)N_NODES * 256];  // x fp16
__device__ __align__(16) __half g_h0h [(size_t)N_NODES * 160];  // gemm0 out (140, pad 160)
__device__ __align__(16) __half g_h1h [(size_t)N_NODES * 120];  // hop ping
__device__ __align__(16) __half g_h2h [(size_t)N_NODES * 120];  // hop pong
__device__ __align__(16) __half g_l1h [(size_t)N_NODES * 128];  // ln1 out (120, pad 128)
__device__ __align__(16) __half g_l2h [(size_t)N_NODES * 128];  // ln2 out (100, pad 128)
__device__ __align__(16) float  g_hf1 [(size_t)N_NODES * 120];  // fp32 pre-LN buf
__device__ __align__(16) float  g_hf2 [(size_t)N_NODES * 120];
__device__ int   g_rowptr[N_NODES + 1];
__device__ __align__(16) __half g_Wph  [256 * 192];             // folded W_in fp16
__device__ __align__(16) __half g_W1h  [160 * 128];
__device__ __align__(16) __half g_W2h  [128 * 128];
__device__ __align__(16) __half g_Woh  [128 * 64];
__device__ float g_bp[144];
__device__ float g_part[2 * 512 * 256];
__device__ float g_scale[IN_DIM];
__device__ float g_shift[IN_DIM];

// ---------------- CSR row_ptr via binary search over sorted rows --------------
__global__ void build_rowptr_kernel(const int* __restrict__ rows) {
    int r = blockIdx.x * blockDim.x + threadIdx.x;
    if (r > N_NODES) return;
    int lo = 0, hi = N_EDGES;
    while (lo < hi) {
        int mid = (lo + hi) >> 1;
        if (rows[mid] < r) lo = mid + 1; else hi = mid;
    }
    g_rowptr[r] = lo;
}

// -------- BatchNorm partials + fp16 conversion of x (fused) -------------------
__global__ void bn_partial_conv_kernel(const float* __restrict__ x) {
    const int CHUNK = (N_NODES + 511) / 512;
    int c = threadIdx.x;
    int b = blockIdx.x;
    int r0 = b * CHUNK;
    int r1 = r0 + CHUNK; if (r1 > N_NODES) r1 = N_NODES;
    float s = 0.f, s2 = 0.f;
    for (int r = r0; r < r1; r++) {
        float v = x[(size_t)r * IN_DIM + c];
        s += v; s2 += v * v;
        g_xh[(size_t)r * IN_DIM + c] = __float2half_rn(v);
    }
    g_part[b * 256 + c]          = s;
    g_part[131072 + b * 256 + c] = s2;
}

__global__ void bn_finalize_kernel(const float* __restrict__ bn_g,
                                   const float* __restrict__ bn_b) {
    int c = threadIdx.x;
    float s = 0.f, s2 = 0.f;
    for (int b = 0; b < 512; b++) {
        s  += g_part[b * 256 + c];
        s2 += g_part[131072 + b * 256 + c];
    }
    float mean = s / (float)N_NODES;
    float var  = s2 / (float)N_NODES - mean * mean;
    float sc   = rsqrtf(var + EPS) * bn_g[c];
    g_scale[c] = sc;
    g_shift[c] = bn_b[c] - mean * sc;
}

// Fold BN into W_in (fp16 padded [256][192]) + folded bias
__global__ void fold_kernel(const float* __restrict__ W,
                            const float* __restrict__ b_in) {
    if (blockIdx.x < 192) {
        int i = blockIdx.x * 256 + threadIdx.x;
        int k = i / 192, n = i % 192;
        float v = (n < 140) ? g_scale[k] * W[k * 140 + n] : 0.f;
        g_Wph[i] = __float2half_rn(v);
    } else {
        int j = threadIdx.x;
        if (j < 144) {
            float acc = (j < 140) ? b_in[j] : 0.f;
            if (j < 140)
                for (int k = 0; k < IN_DIM; k++) acc += g_shift[k] * W[k * 140 + j];
            g_bp[j] = acc;
        }
    }
}

// merged weight convert+pad
__global__ void convw_all_kernel(const float* __restrict__ W1,
                                 const float* __restrict__ W2,
                                 const float* __restrict__ Wo) {
    int i = blockIdx.x * 256 + threadIdx.x;
    if (i < 160 * 128) {
        int k = i / 128, n = i % 128;
        g_W1h[i] = (k < 140 && n < 120) ? __float2half_rn(W1[k * 120 + n]) : __half(0.f);
        return;
    }
    i -= 160 * 128;
    if (i < 128 * 128) {
        int k = i / 128, n = i % 128;
        g_W2h[i] = (k < 120 && n < 100) ? __float2half_rn(W2[k * 100 + n]) : __half(0.f);
        return;
    }
    i -= 128 * 128;
    if (i < 128 * 64) {
        int k = i / 64, n = i % 64;
        g_Woh[i] = (k < 100) ? __float2half_rn(Wo[k * 64 + n]) : __half(0.f);
    }
}

// ------- tensor-core GEMM, 3-stage cp.async pipeline, BK=32 -------------------
// NT = n-subtiles per warp: NT=1 -> BN=64 (warp 32x32), NT=2 -> BN=128 (warp 32x64)
// NT=2 only pays for short-K GEMMs (regs -> 2 CTAs/SM); long-K needs NT=1.
template<bool BIAS, bool TANH, bool OUT_HALF, int NT>
__global__ __launch_bounds__(256)
void mma_gemm_kernel(const __half* __restrict__ A, const __half* __restrict__ B,
                     const float* __restrict__ bias, void* __restrict__ Cv,
                     int M, int N, int Kp, int Np, int outStride, int padTo) {
    const int BN  = 64 * NT;
    const int LDA = 40;          // 80B rows -> ldmatrix conflict-free
    const int LDB = BN + 8;      // NT=1: 72 (144B), NT=2: 136 (272B); same bank shift
    const int ST  = 3;           // pipeline stages
    __shared__ __half As[ST][128 * LDA];
    __shared__ __half Bs[ST][32 * LDB];
    int t = threadIdx.x;
    int lane = t & 31, warp = t >> 5;
    int wm = (warp & 3) * 32, wn = (warp >> 2) * (32 * NT);
    int bm = blockIdx.x * 128, bn = blockIdx.y * BN;

    float c[2][4 * NT][4];
    #pragma unroll
    for (int mi = 0; mi < 2; mi++)
        #pragma unroll
        for (int ni = 0; ni < 4 * NT; ni++)
            #pragma unroll
            for (int f = 0; f < 4; f++) c[mi][ni][f] = 0.f;

    uint32_t as_base[ST], bs_base[ST];
    #pragma unroll
    for (int s = 0; s < ST; s++) {
        as_base[s] = (uint32_t)__cvta_generic_to_shared(&As[s][0]);
        bs_base[s] = (uint32_t)__cvta_generic_to_shared(&Bs[s][0]);
    }

    auto load_tiles = [&](int k0, int buf) {
        #pragma unroll
        for (int i = 0; i < 2; i++) {                 // A: 128x32h = 512 x 16B
            int idx = t + i * 256;
            int r = idx >> 2, ch = (idx & 3) * 8;
            const __half* src = A + (size_t)(bm + r) * Kp + k0 + ch;
            uint32_t dst = as_base[buf] + (uint32_t)((r * LDA + ch) * 2);
            int sz = (bm + r < M) ? 16 : 0;
            asm volatile("cp.async.cg.shared.global [%0], [%1], 16, %2;"
                         :: "r"(dst), "l"(src), "r"(sz));
        }
        #pragma unroll
        for (int i = 0; i < NT; i++) {                // B: 32xBN halves
            int idx = t + i * 256;
            int r = idx / (BN / 8);
            int ch = (idx % (BN / 8)) * 8;
            const __half* src = B + (size_t)(k0 + r) * Np + bn + ch;
            uint32_t dst = bs_base[buf] + (uint32_t)((r * LDB + ch) * 2);
            asm volatile("cp.async.cg.shared.global [%0], [%1], 16;"
                         :: "r"(dst), "l"(src));
        }
        asm volatile("cp.async.commit_group;");
    };

    auto compute = [&](int buf) {
        uint32_t a_base = as_base[buf] +
            (uint32_t)(((wm + (lane & 15)) * LDA + (lane >> 4) * 8) * 2);
        uint32_t b_base = bs_base[buf] +
            (uint32_t)(((lane & 15) * LDB + wn) * 2);
        #pragma unroll
        for (int ks = 0; ks < 32; ks += 16) {
            uint32_t a[2][4], bf[4 * NT][2];
            #pragma unroll
            for (int mi = 0; mi < 2; mi++) {
                uint32_t addr = a_base + (uint32_t)((mi * 16 * LDA + ks) * 2);
                asm volatile("ldmatrix.sync.aligned.m8n8.x4.shared.b16 {%0,%1,%2,%3}, [%4];"
                             : "=r"(a[mi][0]), "=r"(a[mi][1]), "=r"(a[mi][2]), "=r"(a[mi][3])
                             : "r"(addr));
            }
            #pragma unroll
            for (int ni = 0; ni < 4 * NT; ni++) {
                uint32_t addr = b_base + (uint32_t)((ks * LDB + ni * 8) * 2);
                asm volatile("ldmatrix.sync.aligned.m8n8.x2.trans.shared.b16 {%0,%1}, [%2];"
                             : "=r"(bf[ni][0]), "=r"(bf[ni][1]) : "r"(addr));
            }
            #pragma unroll
            for (int mi = 0; mi < 2; mi++)
                #pragma unroll
                for (int ni = 0; ni < 4 * NT; ni++) {
                    asm volatile(
                        "mma.sync.aligned.m16n8k16.row.col.f32.f16.f16.f32 "
                        "{%0,%1,%2,%3}, {%4,%5,%6,%7}, {%8,%9}, {%0,%1,%2,%3};"
                        : "+f"(c[mi][ni][0]), "+f"(c[mi][ni][1]),
                          "+f"(c[mi][ni][2]), "+f"(c[mi][ni][3])
                        : "r"(a[mi][0]), "r"(a[mi][1]), "r"(a[mi][2]), "r"(a[mi][3]),
                          "r"(bf[ni][0]), "r"(bf[ni][1]));
                }
        }
    };

    int nIter = Kp >> 5;
    load_tiles(0, 0);
    if (nIter > 1) load_tiles(32, 1);
    for (int it = 0; it < nIter; it++) {
        if (it + 2 < nIter) load_tiles((it + 2) << 5, (it + 2) % ST);
        // wait until group `it` is complete: newer pending groups = min(nIter-1, it+2) - it
        int newer = nIter - 1 - it;
        if (newer >= 2)      asm volatile("cp.async.wait_group 2;");
        else if (newer == 1) asm volatile("cp.async.wait_group 1;");
        else                 asm volatile("cp.async.wait_group 0;");
        __syncthreads();
        compute(it % ST);
        __syncthreads();
    }

    int r0 = bm + wm + (lane >> 2);
    int col0 = bn + wn + (lane & 3) * 2;
    #pragma unroll
    for (int mi = 0; mi < 2; mi++)
        #pragma unroll
        for (int ni = 0; ni < 4 * NT; ni++)
            #pragma unroll
            for (int hr = 0; hr < 2; hr++) {
                int r = r0 + mi * 16 + hr * 8;
                int col = col0 + ni * 8;
                if (r >= M || col >= padTo) continue;
                float v0 = c[mi][ni][hr * 2 + 0];
                float v1 = c[mi][ni][hr * 2 + 1];
                if (col < N) {
                    if (BIAS) { v0 += bias[col]; v1 += bias[col + 1]; }
                    if (TANH) { v0 = tanhf(v0); v1 = tanhf(v1); }
                } else { v0 = 0.f; v1 = 0.f; }
                if (OUT_HALF) {
                    __half2 p = __floats2half2_rn(v0, v1);
                    *(__half2*)((__half*)Cv + (size_t)r * outStride + col) = p;
                } else {
                    float2 p; p.x = v0; p.y = v1;
                    *(float2*)((float*)Cv + (size_t)r * outStride + col) = p;
                }
            }
}

// ---------------- SpMM: warp per row, fp16 X, fp32 accum, 4-edge unroll -------
// EXACT R4 loop (scalar col/val LDGs — measured local optimum; do not touch).
template<int LANES, bool OUT_FLOAT>
__global__ __launch_bounds__(256)
void spmm_h_kernel(const int* __restrict__ cols, const float* __restrict__ vals,
                   const __half* __restrict__ X, void* __restrict__ Yv) {
    int w = (int)((blockIdx.x * blockDim.x + threadIdx.x) >> 5);
    if (w >= N_NODES) return;
    int lane = threadIdx.x & 31;
    int l = lane < LANES ? lane : 0;
    int e0 = g_rowptr[w], e1 = g_rowptr[w + 1];
    const uint2* __restrict__ X2 = (const uint2*)X;
    float4 acc  = make_float4(0.f, 0.f, 0.f, 0.f);
    float4 acc2 = make_float4(0.f, 0.f, 0.f, 0.f);
    int e = e0;
    for (; e + 4 <= e1; e += 4) {
        int   c0 = __ldg(cols + e),     c1 = __ldg(cols + e + 1);
        int   c2 = __ldg(cols + e + 2), c3 = __ldg(cols + e + 3);
        float v0 = __ldg(vals + e),     v1 = __ldg(vals + e + 1);
        float v2 = __ldg(vals + e + 2), v3 = __ldg(vals + e + 3);
        uint2 p0 = X2[(size_t)c0 * LANES + l];
        uint2 p1 = X2[(size_t)c1 * LANES + l];
        uint2 p2 = X2[(size_t)c2 * LANES + l];
        uint2 p3 = X2[(size_t)c3 * LANES + l];
        float2 a0 = __half22float2(*(const __half2*)&p0.x);
        float2 b0 = __half22float2(*(const __half2*)&p0.y);
        float2 a1 = __half22float2(*(const __half2*)&p1.x);
        float2 b1 = __half22float2(*(const __half2*)&p1.y);
        float2 a2 = __half22float2(*(const __half2*)&p2.x);
        float2 b2 = __half22float2(*(const __half2*)&p2.y);
        float2 a3 = __half22float2(*(const __half2*)&p3.x);
        float2 b3 = __half22float2(*(const __half2*)&p3.y);
        acc.x  = fmaf(v0, a0.x, acc.x);   acc.y  = fmaf(v0, a0.y, acc.y);
        acc.z  = fmaf(v0, b0.x, acc.z);   acc.w  = fmaf(v0, b0.y, acc.w);
        acc2.x = fmaf(v1, a1.x, acc2.x);  acc2.y = fmaf(v1, a1.y, acc2.y);
        acc2.z = fmaf(v1, b1.x, acc2.z);  acc2.w = fmaf(v1, b1.y, acc2.w);
        acc.x  = fmaf(v2, a2.x, acc.x);   acc.y  = fmaf(v2, a2.y, acc.y);
        acc.z  = fmaf(v2, b2.x, acc.z);   acc.w  = fmaf(v2, b2.y, acc.w);
        acc2.x = fmaf(v3, a3.x, acc2.x);  acc2.y = fmaf(v3, a3.y, acc2.y);
        acc2.z = fmaf(v3, b3.x, acc2.z);  acc2.w = fmaf(v3, b3.y, acc2.w);
    }
    for (; e < e1; e++) {
        int   c0 = __ldg(cols + e);
        float v0 = __ldg(vals + e);
        uint2 p0 = X2[(size_t)c0 * LANES + l];
        float2 a0 = __half22float2(*(const __half2*)&p0.x);
        float2 b0 = __half22float2(*(const __half2*)&p0.y);
        acc.x = fmaf(v0, a0.x, acc.x);  acc.y = fmaf(v0, a0.y, acc.y);
        acc.z = fmaf(v0, b0.x, acc.z);  acc.w = fmaf(v0, b0.y, acc.w);
    }
    acc.x += acc2.x; acc.y += acc2.y; acc.z += acc2.z; acc.w += acc2.w;
    if (lane < LANES) {
        if (OUT_FLOAT) {
            float4* Y = (float4*)Yv;
            Y[(size_t)w * LANES + lane] = acc;
        } else {
            __half2 o0 = __floats2half2_rn(acc.x, acc.y);
            __half2 o1 = __floats2half2_rn(acc.z, acc.w);
            uint2 pk;
            pk.x = *(const unsigned*)&o0;
            pk.y = *(const unsigned*)&o1;
            ((uint2*)Yv)[(size_t)w * LANES + lane] = pk;
        }
    }
}

// ------- (+bias) LayerNorm + tanh, warp per row, fp32 in -> fp16 padded out ---
template<int F, int PADF>
__global__ __launch_bounds__(256)
void ln_tanh_kernel(const float* __restrict__ H, const float* __restrict__ pre_bias,
                    const float* __restrict__ g, const float* __restrict__ b,
                    __half* __restrict__ L) {
    int w = (int)((blockIdx.x * blockDim.x + threadIdx.x) >> 5);
    if (w >= N_NODES) return;
    int lane = threadIdx.x & 31;
    const int NI = (F + 31) / 32;
    float v[NI];
    float sum = 0.f;
    #pragma unroll
    for (int i = 0; i < NI; i++) {
        int f = lane + i * 32;
        v[i] = (f < F) ? H[(size_t)w * F + f] + pre_bias[f] : 0.f;
        sum += v[i];
    }
    #pragma unroll
    for (int o = 16; o; o >>= 1) sum += __shfl_xor_sync(0xFFFFFFFFu, sum, o);
    float mean = sum / (float)F;
    float vs = 0.f;
    #pragma unroll
    for (int i = 0; i < NI; i++) {
        int f = lane + i * 32;
        if (f < F) { float d = v[i] - mean; vs += d * d; }
    }
    #pragma unroll
    for (int o = 16; o; o >>= 1) vs += __shfl_xor_sync(0xFFFFFFFFu, vs, o);
    float rstd = rsqrtf(vs / (float)F + EPS);
    const int NO = PADF / 32;
    #pragma unroll
    for (int i = 0; i < NO; i++) {
        int f = lane + i * 32;
        float o = (f < F) ? tanhf((v[i] - mean) * rstd * g[f] + b[f]) : 0.f;
        L[(size_t)w * PADF + f] = __float2half_rn(o);
    }
}

// ---------------- launch ------------------------------------------------------
extern "C" void kernel_launch(void* const* d_in, const int* in_sizes, int n_in,
                              void* d_out, int out_size) {
    const float* x        = (const float*)d_in[0];
    const float* adj_vals = (const float*)d_in[1];
    const float* bn_g     = (const float*)d_in[2];
    const float* bn_b     = (const float*)d_in[3];
    const float* W_in     = (const float*)d_in[4];
    const float* b_in     = (const float*)d_in[5];
    const float* W1       = (const float*)d_in[6];
    const float* b1       = (const float*)d_in[7];
    const float* ln1_g    = (const float*)d_in[8];
    const float* ln1_b    = (const float*)d_in[9];
    const float* W2       = (const float*)d_in[10];
    const float* b2       = (const float*)d_in[11];
    const float* ln2_g    = (const float*)d_in[12];
    const float* ln2_b    = (const float*)d_in[13];
    const float* W_out    = (const float*)d_in[14];
    const float* b_out    = (const float*)d_in[15];
    const int*   adj_rows = (const int*)d_in[16];
    const int*   adj_cols = (const int*)d_in[17];
    float* out = (float*)d_out;

    void *p_xh, *p_h0h, *p_h1h, *p_h2h, *p_l1h, *p_l2h, *p_hf1, *p_hf2;
    void *p_Wph, *p_W1h, *p_W2h, *p_Woh, *p_bp;
    cudaGetSymbolAddress(&p_xh,  g_xh);
    cudaGetSymbolAddress(&p_h0h, g_h0h);
    cudaGetSymbolAddress(&p_h1h, g_h1h);
    cudaGetSymbolAddress(&p_h2h, g_h2h);
    cudaGetSymbolAddress(&p_l1h, g_l1h);
    cudaGetSymbolAddress(&p_l2h, g_l2h);
    cudaGetSymbolAddress(&p_hf1, g_hf1);
    cudaGetSymbolAddress(&p_hf2, g_hf2);
    cudaGetSymbolAddress(&p_Wph, g_Wph);
    cudaGetSymbolAddress(&p_W1h, g_W1h);
    cudaGetSymbolAddress(&p_W2h, g_W2h);
    cudaGetSymbolAddress(&p_Woh, g_Woh);
    cudaGetSymbolAddress(&p_bp,  g_bp);
    __half* xh  = (__half*)p_xh;
    __half* h0h = (__half*)p_h0h;
    __half* h1h = (__half*)p_h1h;
    __half* h2h = (__half*)p_h2h;
    __half* l1h = (__half*)p_l1h;
    __half* l2h = (__half*)p_l2h;
    float*  hf1 = (float*)p_hf1;
    float*  hf2 = (float*)p_hf2;
    __half* Wph = (__half*)p_Wph;
    __half* W1h = (__half*)p_W1h;
    __half* W2h = (__half*)p_W2h;
    __half* Woh = (__half*)p_Woh;
    float*  bp  = (float*)p_bp;

    const int GM = (N_NODES + 127) / 128;
    const int WARP_GRID = (N_NODES * 32 + 255) / 256;

    bn_partial_conv_kernel<<<512, 256>>>(x);
    bn_finalize_kernel<<<1, 256>>>(bn_g, bn_b);
    fold_kernel<<<193, 256>>>(W_in, b_in);

    // h0h = tanh(bn(x) @ W_in + b_in)  [N,140] fp16, stride 160  (NT=1, y=3)
    mma_gemm_kernel<true, true, true, 1><<<dim3(GM, 3), 256>>>(
        xh, Wph, bp, h0h, N_NODES, 140, 256, 192, 160, 160);

    convw_all_kernel<<<(160 * 128 + 128 * 128 + 128 * 64 + 255) / 256, 256>>>(W1, W2, W_out);
    build_rowptr_kernel<<<(N_NODES + 256) / 256, 256>>>(adj_rows);

    // h1h = h0h @ W1 (bias deferred)  [N,120] fp16, stride 120  (NT=2, short K)
    mma_gemm_kernel<false, false, true, 2><<<dim3(GM, 1), 256>>>(
        h0h, W1h, nullptr, h1h, N_NODES, 120, 160, 128, 120, 120);

    // 4 hops @ F=120; 4th writes fp32 (values ~16^4 exceed fp16 range)
    spmm_h_kernel<30, false><<<WARP_GRID, 256>>>(adj_cols, adj_vals, h1h, h2h);
    spmm_h_kernel<30, false><<<WARP_GRID, 256>>>(adj_cols, adj_vals, h2h, h1h);
    spmm_h_kernel<30, false><<<WARP_GRID, 256>>>(adj_cols, adj_vals, h1h, h2h);
    spmm_h_kernel<30, true ><<<WARP_GRID, 256>>>(adj_cols, adj_vals, h2h, hf1);

    // ln1: fp32 -> fp16 padded [N,128]
    ln_tanh_kernel<120, 128><<<WARP_GRID, 256>>>(hf1, b1, ln1_g, ln1_b, l1h);

    // gemm2 -> [N,100] fp16, stride 100 (into h1h)  (NT=2, short K)
    mma_gemm_kernel<false, false, true, 2><<<dim3(GM, 1), 256>>>(
        l1h, W2h, nullptr, h1h, N_NODES, 100, 128, 128, 100, 100);

    // 4 hops @ F=100; 4th writes fp32
    spmm_h_kernel<25, false><<<WARP_GRID, 256>>>(adj_cols, adj_vals, h1h, h2h);
    spmm_h_kernel<25, false><<<WARP_GRID, 256>>>(adj_cols, adj_vals, h2h, h1h);
    spmm_h_kernel<25, false><<<WARP_GRID, 256>>>(adj_cols, adj_vals, h1h, h2h);
    spmm_h_kernel<25, true ><<<WARP_GRID, 256>>>(adj_cols, adj_vals, h2h, hf2);

    // ln2: fp32 -> fp16 padded [N,128]
    ln_tanh_kernel<100, 128><<<WARP_GRID, 256>>>(hf2, b2, ln2_g, ln2_b, l2h);

    // out = l2 @ W_out + b_out  [N,64] fp32  (NT=1)
    mma_gemm_kernel<true, false, false, 1><<<dim3(GM, 1), 256>>>(
        l2h, Woh, b_out, out, N_NODES, 64, 128, 64, 64, 64);
}

// round 15
// speedup vs baseline: 1.0004x; 1.0004x over previous
#include <cuda_runtime.h>
#include <cuda_fp16.h>
#include <cstdint>

#define N_NODES 100000
#define N_EDGES 3200000
#define IN_DIM  256
#define EPS     1e-5f

// ---------------- scratch (__device__ globals; no allocations) ----------------
__device__ __align__(16) __half g_xh  [(size_t)N_NODES * 256];  // x fp16
__device__ __align__(16) __half g_h0h [(size_t)N_NODES * 160];  // gemm0 out (140, pad 160)
__device__ __align__(16) __half g_h1h [(size_t)N_NODES * 120];  // hop ping
__device__ __align__(16) __half g_h2h [(size_t)N_NODES * 120];  // hop pong
__device__ __align__(16) __half g_l1h [(size_t)N_NODES * 128];  // ln1 out (120, pad 128)
__device__ __align__(16) __half g_l2h [(size_t)N_NODES * 128];  // ln2 out (100, pad 128)
__device__ __align__(16) float  g_hf1 [(size_t)N_NODES * 120];  // fp32 pre-LN buf
__device__ __align__(16) float  g_hf2 [(size_t)N_NODES * 120];
__device__ int   g_rowptr[N_NODES + 1];
__device__ __align__(16) __half g_Wph  [256 * 192];             // folded W_in fp16
__device__ __align__(16) __half g_W1h  [160 * 128];
__device__ __align__(16) __half g_W2h  [128 * 128];
__device__ __align__(16) __half g_Woh  [128 * 64];
__device__ float g_bp[144];
__device__ float g_part[2 * 512 * 256];
__device__ float g_scale[IN_DIM];
__device__ float g_shift[IN_DIM];

// -------- BatchNorm partials + fp16 conversion of x (fused) -------------------
__global__ void bn_partial_conv_kernel(const float* __restrict__ x) {
    const int CHUNK = (N_NODES + 511) / 512;
    int c = threadIdx.x;
    int b = blockIdx.x;
    int r0 = b * CHUNK;
    int r1 = r0 + CHUNK; if (r1 > N_NODES) r1 = N_NODES;
    float s = 0.f, s2 = 0.f;
    for (int r = r0; r < r1; r++) {
        float v = x[(size_t)r * IN_DIM + c];
        s += v; s2 += v * v;
        g_xh[(size_t)r * IN_DIM + c] = __float2half_rn(v);
    }
    g_part[b * 256 + c]          = s;
    g_part[131072 + b * 256 + c] = s2;
}

__global__ void bn_finalize_kernel(const float* __restrict__ bn_g,
                                   const float* __restrict__ bn_b) {
    int c = threadIdx.x;
    float s = 0.f, s2 = 0.f;
    for (int b = 0; b < 512; b++) {
        s  += g_part[b * 256 + c];
        s2 += g_part[131072 + b * 256 + c];
    }
    float mean = s / (float)N_NODES;
    float var  = s2 / (float)N_NODES - mean * mean;
    float sc   = rsqrtf(var + EPS) * bn_g[c];
    g_scale[c] = sc;
    g_shift[c] = bn_b[c] - mean * sc;
}

// Fold BN into W_in (fp16 padded [256][192]) + folded bias
__global__ void fold_kernel(const float* __restrict__ W,
                            const float* __restrict__ b_in) {
    if (blockIdx.x < 192) {
        int i = blockIdx.x * 256 + threadIdx.x;
        int k = i / 192, n = i % 192;
        float v = (n < 140) ? g_scale[k] * W[k * 140 + n] : 0.f;
        g_Wph[i] = __float2half_rn(v);
    } else {
        int j = threadIdx.x;
        if (j < 144) {
            float acc = (j < 140) ? b_in[j] : 0.f;
            if (j < 140)
                for (int k = 0; k < IN_DIM; k++) acc += g_shift[k] * W[k * 140 + j];
            g_bp[j] = acc;
        }
    }
}

// merged: weight convert+pad (blocks 0..175) + CSR rowptr (blocks 176..566)
__global__ void setup_kernel(const float* __restrict__ W1,
                             const float* __restrict__ W2,
                             const float* __restrict__ Wo,
                             const int* __restrict__ rows) {
    if (blockIdx.x < 176) {
        int i = blockIdx.x * 256 + threadIdx.x;
        if (i < 160 * 128) {
            int k = i / 128, n = i % 128;
            g_W1h[i] = (k < 140 && n < 120) ? __float2half_rn(W1[k * 120 + n]) : __half(0.f);
            return;
        }
        i -= 160 * 128;
        if (i < 128 * 128) {
            int k = i / 128, n = i % 128;
            g_W2h[i] = (k < 120 && n < 100) ? __float2half_rn(W2[k * 100 + n]) : __half(0.f);
            return;
        }
        i -= 128 * 128;
        if (i < 128 * 64) {
            int k = i / 64, n = i % 64;
            g_Woh[i] = (k < 100) ? __float2half_rn(Wo[k * 64 + n]) : __half(0.f);
        }
    } else {
        int r = (blockIdx.x - 176) * 256 + threadIdx.x;
        if (r > N_NODES) return;
        int lo = 0, hi = N_EDGES;
        while (lo < hi) {
            int mid = (lo + hi) >> 1;
            if (rows[mid] < r) lo = mid + 1; else hi = mid;
        }
        g_rowptr[r] = lo;
    }
}

// ------- tensor-core GEMM, double-buffered cp.async, BK=32 --------------------
// NT = n-subtiles per warp: NT=1 -> BN=64 (warp 32x32), NT=2 -> BN=128 (warp 32x64)
// NT=2 only pays for short-K GEMMs; long-K needs NT=1 (occupancy). 2 stages are
// optimal (3-stage measured neutral-negative: stage-index ALU eats the gain).
template<bool BIAS, bool TANH, bool OUT_HALF, int NT>
__global__ __launch_bounds__(256)
void mma_gemm_kernel(const __half* __restrict__ A, const __half* __restrict__ B,
                     const float* __restrict__ bias, void* __restrict__ Cv,
                     int M, int N, int Kp, int Np, int outStride, int padTo) {
    const int BN  = 64 * NT;
    const int LDA = 40;          // 80B rows -> ldmatrix conflict-free
    const int LDB = BN + 8;      // NT=1: 72 (144B), NT=2: 136 (272B); same bank shift
    __shared__ __half As[2][128 * LDA];
    __shared__ __half Bs[2][32 * LDB];
    int t = threadIdx.x;
    int lane = t & 31, warp = t >> 5;
    int wm = (warp & 3) * 32, wn = (warp >> 2) * (32 * NT);
    int bm = blockIdx.x * 128, bn = blockIdx.y * BN;

    float c[2][4 * NT][4];
    #pragma unroll
    for (int mi = 0; mi < 2; mi++)
        #pragma unroll
        for (int ni = 0; ni < 4 * NT; ni++)
            #pragma unroll
            for (int f = 0; f < 4; f++) c[mi][ni][f] = 0.f;

    uint32_t as_base[2], bs_base[2];
    as_base[0] = (uint32_t)__cvta_generic_to_shared(&As[0][0]);
    as_base[1] = (uint32_t)__cvta_generic_to_shared(&As[1][0]);
    bs_base[0] = (uint32_t)__cvta_generic_to_shared(&Bs[0][0]);
    bs_base[1] = (uint32_t)__cvta_generic_to_shared(&Bs[1][0]);

    auto load_tiles = [&](int k0, int buf) {
        #pragma unroll
        for (int i = 0; i < 2; i++) {                 // A: 128x32h = 512 x 16B
            int idx = t + i * 256;
            int r = idx >> 2, ch = (idx & 3) * 8;
            const __half* src = A + (size_t)(bm + r) * Kp + k0 + ch;
            uint32_t dst = as_base[buf] + (uint32_t)((r * LDA + ch) * 2);
            int sz = (bm + r < M) ? 16 : 0;
            asm volatile("cp.async.cg.shared.global [%0], [%1], 16, %2;"
                         :: "r"(dst), "l"(src), "r"(sz));
        }
        #pragma unroll
        for (int i = 0; i < NT; i++) {                // B: 32xBN halves
            int idx = t + i * 256;
            int r = idx / (BN / 8);
            int ch = (idx % (BN / 8)) * 8;
            const __half* src = B + (size_t)(k0 + r) * Np + bn + ch;
            uint32_t dst = bs_base[buf] + (uint32_t)((r * LDB + ch) * 2);
            asm volatile("cp.async.cg.shared.global [%0], [%1], 16;"
                         :: "r"(dst), "l"(src));
        }
        asm volatile("cp.async.commit_group;");
    };

    auto compute = [&](int buf) {
        uint32_t a_base = as_base[buf] +
            (uint32_t)(((wm + (lane & 15)) * LDA + (lane >> 4) * 8) * 2);
        uint32_t b_base = bs_base[buf] +
            (uint32_t)(((lane & 15) * LDB + wn) * 2);
        #pragma unroll
        for (int ks = 0; ks < 32; ks += 16) {
            uint32_t a[2][4], bf[4 * NT][2];
            #pragma unroll
            for (int mi = 0; mi < 2; mi++) {
                uint32_t addr = a_base + (uint32_t)((mi * 16 * LDA + ks) * 2);
                asm volatile("ldmatrix.sync.aligned.m8n8.x4.shared.b16 {%0,%1,%2,%3}, [%4];"
                             : "=r"(a[mi][0]), "=r"(a[mi][1]), "=r"(a[mi][2]), "=r"(a[mi][3])
                             : "r"(addr));
            }
            #pragma unroll
            for (int ni = 0; ni < 4 * NT; ni++) {
                uint32_t addr = b_base + (uint32_t)((ks * LDB + ni * 8) * 2);
                asm volatile("ldmatrix.sync.aligned.m8n8.x2.trans.shared.b16 {%0,%1}, [%2];"
                             : "=r"(bf[ni][0]), "=r"(bf[ni][1]) : "r"(addr));
            }
            #pragma unroll
            for (int mi = 0; mi < 2; mi++)
                #pragma unroll
                for (int ni = 0; ni < 4 * NT; ni++) {
                    asm volatile(
                        "mma.sync.aligned.m16n8k16.row.col.f32.f16.f16.f32 "
                        "{%0,%1,%2,%3}, {%4,%5,%6,%7}, {%8,%9}, {%0,%1,%2,%3};"
                        : "+f"(c[mi][ni][0]), "+f"(c[mi][ni][1]),
                          "+f"(c[mi][ni][2]), "+f"(c[mi][ni][3])
                        : "r"(a[mi][0]), "r"(a[mi][1]), "r"(a[mi][2]), "r"(a[mi][3]),
                          "r"(bf[ni][0]), "r"(bf[ni][1]));
                }
        }
    };

    int nIter = Kp >> 5;
    load_tiles(0, 0);
    for (int it = 0; it < nIter; it++) {
        int buf = it & 1;
        if (it + 1 < nIter) {
            load_tiles((it + 1) << 5, buf ^ 1);
            asm volatile("cp.async.wait_group 1;");
        } else {
            asm volatile("cp.async.wait_group 0;");
        }
        __syncthreads();
        compute(buf);
        __syncthreads();
    }

    int r0 = bm + wm + (lane >> 2);
    int col0 = bn + wn + (lane & 3) * 2;
    #pragma unroll
    for (int mi = 0; mi < 2; mi++)
        #pragma unroll
        for (int ni = 0; ni < 4 * NT; ni++)
            #pragma unroll
            for (int hr = 0; hr < 2; hr++) {
                int r = r0 + mi * 16 + hr * 8;
                int col = col0 + ni * 8;
                if (r >= M || col >= padTo) continue;
                float v0 = c[mi][ni][hr * 2 + 0];
                float v1 = c[mi][ni][hr * 2 + 1];
                if (col < N) {
                    if (BIAS) { v0 += bias[col]; v1 += bias[col + 1]; }
                    if (TANH) { v0 = tanhf(v0); v1 = tanhf(v1); }
                } else { v0 = 0.f; v1 = 0.f; }
                if (OUT_HALF) {
                    __half2 p = __floats2half2_rn(v0, v1);
                    *(__half2*)((__half*)Cv + (size_t)r * outStride + col) = p;
                } else {
                    float2 p; p.x = v0; p.y = v1;
                    *(float2*)((float*)Cv + (size_t)r * outStride + col) = p;
                }
            }
}

// ---------------- SpMM: warp per row, fp16 X, fp32 accum, 4-edge unroll -------
// EXACT R4 loop (scalar col/val LDGs — measured local optimum; do not touch).
template<int LANES, bool OUT_FLOAT>
__global__ __launch_bounds__(256)
void spmm_h_kernel(const int* __restrict__ cols, const float* __restrict__ vals,
                   const __half* __restrict__ X, void* __restrict__ Yv) {
    int w = (int)((blockIdx.x * blockDim.x + threadIdx.x) >> 5);
    if (w >= N_NODES) return;
    int lane = threadIdx.x & 31;
    int l = lane < LANES ? lane : 0;
    int e0 = g_rowptr[w], e1 = g_rowptr[w + 1];
    const uint2* __restrict__ X2 = (const uint2*)X;
    float4 acc  = make_float4(0.f, 0.f, 0.f, 0.f);
    float4 acc2 = make_float4(0.f, 0.f, 0.f, 0.f);
    int e = e0;
    for (; e + 4 <= e1; e += 4) {
        int   c0 = __ldg(cols + e),     c1 = __ldg(cols + e + 1);
        int   c2 = __ldg(cols + e + 2), c3 = __ldg(cols + e + 3);
        float v0 = __ldg(vals + e),     v1 = __ldg(vals + e + 1);
        float v2 = __ldg(vals + e + 2), v3 = __ldg(vals + e + 3);
        uint2 p0 = X2[(size_t)c0 * LANES + l];
        uint2 p1 = X2[(size_t)c1 * LANES + l];
        uint2 p2 = X2[(size_t)c2 * LANES + l];
        uint2 p3 = X2[(size_t)c3 * LANES + l];
        float2 a0 = __half22float2(*(const __half2*)&p0.x);
        float2 b0 = __half22float2(*(const __half2*)&p0.y);
        float2 a1 = __half22float2(*(const __half2*)&p1.x);
        float2 b1 = __half22float2(*(const __half2*)&p1.y);
        float2 a2 = __half22float2(*(const __half2*)&p2.x);
        float2 b2 = __half22float2(*(const __half2*)&p2.y);
        float2 a3 = __half22float2(*(const __half2*)&p3.x);
        float2 b3 = __half22float2(*(const __half2*)&p3.y);
        acc.x  = fmaf(v0, a0.x, acc.x);   acc.y  = fmaf(v0, a0.y, acc.y);
        acc.z  = fmaf(v0, b0.x, acc.z);   acc.w  = fmaf(v0, b0.y, acc.w);
        acc2.x = fmaf(v1, a1.x, acc2.x);  acc2.y = fmaf(v1, a1.y, acc2.y);
        acc2.z = fmaf(v1, b1.x, acc2.z);  acc2.w = fmaf(v1, b1.y, acc2.w);
        acc.x  = fmaf(v2, a2.x, acc.x);   acc.y  = fmaf(v2, a2.y, acc.y);
        acc.z  = fmaf(v2, b2.x, acc.z);   acc.w  = fmaf(v2, b2.y, acc.w);
        acc2.x = fmaf(v3, a3.x, acc2.x);  acc2.y = fmaf(v3, a3.y, acc2.y);
        acc2.z = fmaf(v3, b3.x, acc2.z);  acc2.w = fmaf(v3, b3.y, acc2.w);
    }
    for (; e < e1; e++) {
        int   c0 = __ldg(cols + e);
        float v0 = __ldg(vals + e);
        uint2 p0 = X2[(size_t)c0 * LANES + l];
        float2 a0 = __half22float2(*(const __half2*)&p0.x);
        float2 b0 = __half22float2(*(const __half2*)&p0.y);
        acc.x = fmaf(v0, a0.x, acc.x);  acc.y = fmaf(v0, a0.y, acc.y);
        acc.z = fmaf(v0, b0.x, acc.z);  acc.w = fmaf(v0, b0.y, acc.w);
    }
    acc.x += acc2.x; acc.y += acc2.y; acc.z += acc2.z; acc.w += acc2.w;
    if (lane < LANES) {
        if (OUT_FLOAT) {
            float4* Y = (float4*)Yv;
            Y[(size_t)w * LANES + lane] = acc;
        } else {
            __half2 o0 = __floats2half2_rn(acc.x, acc.y);
            __half2 o1 = __floats2half2_rn(acc.z, acc.w);
            uint2 pk;
            pk.x = *(const unsigned*)&o0;
            pk.y = *(const unsigned*)&o1;
            ((uint2*)Yv)[(size_t)w * LANES + lane] = pk;
        }
    }
}

// ------- (+bias) LayerNorm + tanh, warp per row, fp32 in -> fp16 padded out ---
template<int F, int PADF>
__global__ __launch_bounds__(256)
void ln_tanh_kernel(const float* __restrict__ H, const float* __restrict__ pre_bias,
                    const float* __restrict__ g, const float* __restrict__ b,
                    __half* __restrict__ L) {
    int w = (int)((blockIdx.x * blockDim.x + threadIdx.x) >> 5);
    if (w >= N_NODES) return;
    int lane = threadIdx.x & 31;
    const int NI = (F + 31) / 32;
    float v[NI];
    float sum = 0.f;
    #pragma unroll
    for (int i = 0; i < NI; i++) {
        int f = lane + i * 32;
        v[i] = (f < F) ? H[(size_t)w * F + f] + pre_bias[f] : 0.f;
        sum += v[i];
    }
    #pragma unroll
    for (int o = 16; o; o >>= 1) sum += __shfl_xor_sync(0xFFFFFFFFu, sum, o);
    float mean = sum / (float)F;
    float vs = 0.f;
    #pragma unroll
    for (int i = 0; i < NI; i++) {
        int f = lane + i * 32;
        if (f < F) { float d = v[i] - mean; vs += d * d; }
    }
    #pragma unroll
    for (int o = 16; o; o >>= 1) vs += __shfl_xor_sync(0xFFFFFFFFu, vs, o);
    float rstd = rsqrtf(vs / (float)F + EPS);
    const int NO = PADF / 32;
    #pragma unroll
    for (int i = 0; i < NO; i++) {
        int f = lane + i * 32;
        float o = (f < F) ? tanhf((v[i] - mean) * rstd * g[f] + b[f]) : 0.f;
        L[(size_t)w * PADF + f] = __float2half_rn(o);
    }
}

// ---------------- launch ------------------------------------------------------
extern "C" void kernel_launch(void* const* d_in, const int* in_sizes, int n_in,
                              void* d_out, int out_size) {
    const float* x        = (const float*)d_in[0];
    const float* adj_vals = (const float*)d_in[1];
    const float* bn_g     = (const float*)d_in[2];
    const float* bn_b     = (const float*)d_in[3];
    const float* W_in     = (const float*)d_in[4];
    const float* b_in     = (const float*)d_in[5];
    const float* W1       = (const float*)d_in[6];
    const float* b1       = (const float*)d_in[7];
    const float* ln1_g    = (const float*)d_in[8];
    const float* ln1_b    = (const float*)d_in[9];
    const float* W2       = (const float*)d_in[10];
    const float* b2       = (const float*)d_in[11];
    const float* ln2_g    = (const float*)d_in[12];
    const float* ln2_b    = (const float*)d_in[13];
    const float* W_out    = (const float*)d_in[14];
    const float* b_out    = (const float*)d_in[15];
    const int*   adj_rows = (const int*)d_in[16];
    const int*   adj_cols = (const int*)d_in[17];
    float* out = (float*)d_out;

    void *p_xh, *p_h0h, *p_h1h, *p_h2h, *p_l1h, *p_l2h, *p_hf1, *p_hf2;
    void *p_Wph, *p_W1h, *p_W2h, *p_Woh, *p_bp;
    cudaGetSymbolAddress(&p_xh,  g_xh);
    cudaGetSymbolAddress(&p_h0h, g_h0h);
    cudaGetSymbolAddress(&p_h1h, g_h1h);
    cudaGetSymbolAddress(&p_h2h, g_h2h);
    cudaGetSymbolAddress(&p_l1h, g_l1h);
    cudaGetSymbolAddress(&p_l2h, g_l2h);
    cudaGetSymbolAddress(&p_hf1, g_hf1);
    cudaGetSymbolAddress(&p_hf2, g_hf2);
    cudaGetSymbolAddress(&p_Wph, g_Wph);
    cudaGetSymbolAddress(&p_W1h, g_W1h);
    cudaGetSymbolAddress(&p_W2h, g_W2h);
    cudaGetSymbolAddress(&p_Woh, g_Woh);
    cudaGetSymbolAddress(&p_bp,  g_bp);
    __half* xh  = (__half*)p_xh;
    __half* h0h = (__half*)p_h0h;
    __half* h1h = (__half*)p_h1h;
    __half* h2h = (__half*)p_h2h;
    __half* l1h = (__half*)p_l1h;
    __half* l2h = (__half*)p_l2h;
    float*  hf1 = (float*)p_hf1;
    float*  hf2 = (float*)p_hf2;
    __half* Wph = (__half*)p_Wph;
    __half* W1h = (__half*)p_W1h;
    __half* W2h = (__half*)p_W2h;
    __half* Woh = (__half*)p_Woh;
    float*  bp  = (float*)p_bp;

    const int GM = (N_NODES + 127) / 128;
    const int WARP_GRID = (N_NODES * 32 + 255) / 256;

    bn_partial_conv_kernel<<<512, 256>>>(x);
    bn_finalize_kernel<<<1, 256>>>(bn_g, bn_b);
    fold_kernel<<<193, 256>>>(W_in, b_in);

    // h0h = tanh(bn(x) @ W_in + b_in)  [N,140] fp16, stride 160  (NT=1, y=3)
    mma_gemm_kernel<true, true, true, 1><<<dim3(GM, 3), 256>>>(
        xh, Wph, bp, h0h, N_NODES, 140, 256, 192, 160, 160);

    // merged weight convert + CSR rowptr (176 + 391 blocks)
    setup_kernel<<<567, 256>>>(W1, W2, W_out, adj_rows);

    // h1h = h0h @ W1 (bias deferred)  [N,120] fp16, stride 120  (NT=2, short K)
    mma_gemm_kernel<false, false, true, 2><<<dim3(GM, 1), 256>>>(
        h0h, W1h, nullptr, h1h, N_NODES, 120, 160, 128, 120, 120);

    // 4 hops @ F=120; 4th writes fp32 (values ~16^4 exceed fp16 range)
    spmm_h_kernel<30, false><<<WARP_GRID, 256>>>(adj_cols, adj_vals, h1h, h2h);
    spmm_h_kernel<30, false><<<WARP_GRID, 256>>>(adj_cols, adj_vals, h2h, h1h);
    spmm_h_kernel<30, false><<<WARP_GRID, 256>>>(adj_cols, adj_vals, h1h, h2h);
    spmm_h_kernel<30, true ><<<WARP_GRID, 256>>>(adj_cols, adj_vals, h2h, hf1);

    // ln1: fp32 -> fp16 padded [N,128]
    ln_tanh_kernel<120, 128><<<WARP_GRID, 256>>>(hf1, b1, ln1_g, ln1_b, l1h);

    // gemm2 -> [N,100] fp16, stride 100 (into h1h)  (NT=2, short K)
    mma_gemm_kernel<false, false, true, 2><<<dim3(GM, 1), 256>>>(
        l1h, W2h, nullptr, h1h, N_NODES, 100, 128, 128, 100, 100);

    // 4 hops @ F=100; 4th writes fp32
    spmm_h_kernel<25, false><<<WARP_GRID, 256>>>(adj_cols, adj_vals, h1h, h2h);
    spmm_h_kernel<25, false><<<WARP_GRID, 256>>>(adj_cols, adj_vals, h2h, h1h);
    spmm_h_kernel<25, false><<<WARP_GRID, 256>>>(adj_cols, adj_vals, h1h, h2h);
    spmm_h_kernel<25, true ><<<WARP_GRID, 256>>>(adj_cols, adj_vals, h2h, hf2);

    // ln2: fp32 -> fp16 padded [N,128]
    ln_tanh_kernel<100, 128><<<WARP_GRID, 256>>>(hf2, b2, ln2_g, ln2_b, l2h);

    // out = l2 @ W_out + b_out  [N,64] fp32  (NT=1)
    mma_gemm_kernel<true, false, false, 1><<<dim3(GM, 1), 256>>>(
        l2h, Woh, b_out, out, N_NODES, 64, 128, 64, 64, 64);
}

// round 16
// speedup vs baseline: 1.0025x; 1.0021x over previous
#include <cuda_runtime.h>
#include <cuda_fp16.h>
#include <cstdint>

#define N_NODES 100000
#define N_EDGES 3200000
#define IN_DIM  256
#define EPS     1e-5f

// ---------------- scratch (__device__ globals; no allocations) ----------------
__device__ __align__(16) __half g_xh  [(size_t)N_NODES * 256];  // x fp16
__device__ __align__(16) __half g_h0h [(size_t)N_NODES * 160];  // gemm0 out (140, pad 160)
__device__ __align__(16) __half g_h1h [(size_t)N_NODES * 120];  // hop ping
__device__ __align__(16) __half g_h2h [(size_t)N_NODES * 120];  // hop pong
__device__ __align__(16) __half g_l1h [(size_t)N_NODES * 128];  // ln1 out (120, pad 128)
__device__ __align__(16) __half g_l2h [(size_t)N_NODES * 128];  // ln2 out (100, pad 128)
__device__ __align__(16) float  g_hf1 [(size_t)N_NODES * 120];  // fp32 pre-LN buf
__device__ __align__(16) float  g_hf2 [(size_t)N_NODES * 120];
__device__ int   g_rowptr[N_NODES + 1];
__device__ __align__(16) __half g_Wph  [256 * 192];             // folded W_in fp16
__device__ __align__(16) __half g_W1h  [160 * 128];
__device__ __align__(16) __half g_W2h  [128 * 128];
__device__ __align__(16) __half g_Woh  [128 * 64];
__device__ float g_bp[144];
__device__ float g_part[2 * 512 * 256];
__device__ float g_scale[IN_DIM];
__device__ float g_shift[IN_DIM];

// -------- BatchNorm partials + fp16 conversion of x (fused) -------------------
__global__ void bn_partial_conv_kernel(const float* __restrict__ x) {
    const int CHUNK = (N_NODES + 511) / 512;
    int c = threadIdx.x;
    int b = blockIdx.x;
    int r0 = b * CHUNK;
    int r1 = r0 + CHUNK; if (r1 > N_NODES) r1 = N_NODES;
    float s = 0.f, s2 = 0.f;
    for (int r = r0; r < r1; r++) {
        float v = x[(size_t)r * IN_DIM + c];
        s += v; s2 += v * v;
        g_xh[(size_t)r * IN_DIM + c] = __float2half_rn(v);
    }
    g_part[b * 256 + c]          = s;
    g_part[131072 + b * 256 + c] = s2;
}

__global__ void bn_finalize_kernel(const float* __restrict__ bn_g,
                                   const float* __restrict__ bn_b) {
    int c = threadIdx.x;
    float s = 0.f, s2 = 0.f;
    for (int b = 0; b < 512; b++) {
        s  += g_part[b * 256 + c];
        s2 += g_part[131072 + b * 256 + c];
    }
    float mean = s / (float)N_NODES;
    float var  = s2 / (float)N_NODES - mean * mean;
    float sc   = rsqrtf(var + EPS) * bn_g[c];
    g_scale[c] = sc;
    g_shift[c] = bn_b[c] - mean * sc;
}

// Fold BN into W_in (fp16 padded [256][192]) + folded bias
__global__ void fold_kernel(const float* __restrict__ W,
                            const float* __restrict__ b_in) {
    if (blockIdx.x < 192) {
        int i = blockIdx.x * 256 + threadIdx.x;
        int k = i / 192, n = i % 192;
        float v = (n < 140) ? g_scale[k] * W[k * 140 + n] : 0.f;
        g_Wph[i] = __float2half_rn(v);
    } else {
        int j = threadIdx.x;
        if (j < 144) {
            float acc = (j < 140) ? b_in[j] : 0.f;
            if (j < 140)
                for (int k = 0; k < IN_DIM; k++) acc += g_shift[k] * W[k * 140 + j];
            g_bp[j] = acc;
        }
    }
}

// merged: weight convert+pad (blocks 0..175) + CSR rowptr (blocks 176..566)
__global__ void setup_kernel(const float* __restrict__ W1,
                             const float* __restrict__ W2,
                             const float* __restrict__ Wo,
                             const int* __restrict__ rows) {
    if (blockIdx.x < 176) {
        int i = blockIdx.x * 256 + threadIdx.x;
        if (i < 160 * 128) {
            int k = i / 128, n = i % 128;
            g_W1h[i] = (k < 140 && n < 120) ? __float2half_rn(W1[k * 120 + n]) : __half(0.f);
            return;
        }
        i -= 160 * 128;
        if (i < 128 * 128) {
            int k = i / 128, n = i % 128;
            g_W2h[i] = (k < 120 && n < 100) ? __float2half_rn(W2[k * 100 + n]) : __half(0.f);
            return;
        }
        i -= 128 * 128;
        if (i < 128 * 64) {
            int k = i / 64, n = i % 64;
            g_Woh[i] = (k < 100) ? __float2half_rn(Wo[k * 64 + n]) : __half(0.f);
        }
    } else {
        int r = (blockIdx.x - 176) * 256 + threadIdx.x;
        if (r > N_NODES) return;
        int lo = 0, hi = N_EDGES;
        while (lo < hi) {
            int mid = (lo + hi) >> 1;
            if (rows[mid] < r) lo = mid + 1; else hi = mid;
        }
        g_rowptr[r] = lo;
    }
}

// ------- tensor-core GEMM, double-buffered cp.async, BK=32 --------------------
// NT = n-subtiles per warp: NT=1 -> BN=64 (warp 32x32), NT=2 -> BN=128 (warp 32x64)
// NT=2 only pays for short-K GEMMs; long-K needs NT=1 (occupancy). 2 stages are
// optimal (3-stage measured neutral-negative: stage-index ALU eats the gain).
template<bool BIAS, bool TANH, bool OUT_HALF, int NT>
__global__ __launch_bounds__(256)
void mma_gemm_kernel(const __half* __restrict__ A, const __half* __restrict__ B,
                     const float* __restrict__ bias, void* __restrict__ Cv,
                     int M, int N, int Kp, int Np, int outStride, int padTo) {
    const int BN  = 64 * NT;
    const int LDA = 40;          // 80B rows -> ldmatrix conflict-free
    const int LDB = BN + 8;      // NT=1: 72 (144B), NT=2: 136 (272B); same bank shift
    __shared__ __half As[2][128 * LDA];
    __shared__ __half Bs[2][32 * LDB];
    int t = threadIdx.x;
    int lane = t & 31, warp = t >> 5;
    int wm = (warp & 3) * 32, wn = (warp >> 2) * (32 * NT);
    int bm = blockIdx.x * 128, bn = blockIdx.y * BN;

    float c[2][4 * NT][4];
    #pragma unroll
    for (int mi = 0; mi < 2; mi++)
        #pragma unroll
        for (int ni = 0; ni < 4 * NT; ni++)
            #pragma unroll
            for (int f = 0; f < 4; f++) c[mi][ni][f] = 0.f;

    uint32_t as_base[2], bs_base[2];
    as_base[0] = (uint32_t)__cvta_generic_to_shared(&As[0][0]);
    as_base[1] = (uint32_t)__cvta_generic_to_shared(&As[1][0]);
    bs_base[0] = (uint32_t)__cvta_generic_to_shared(&Bs[0][0]);
    bs_base[1] = (uint32_t)__cvta_generic_to_shared(&Bs[1][0]);

    auto load_tiles = [&](int k0, int buf) {
        #pragma unroll
        for (int i = 0; i < 2; i++) {                 // A: 128x32h = 512 x 16B
            int idx = t + i * 256;
            int r = idx >> 2, ch = (idx & 3) * 8;
            const __half* src = A + (size_t)(bm + r) * Kp + k0 + ch;
            uint32_t dst = as_base[buf] + (uint32_t)((r * LDA + ch) * 2);
            int sz = (bm + r < M) ? 16 : 0;
            asm volatile("cp.async.cg.shared.global [%0], [%1], 16, %2;"
                         :: "r"(dst), "l"(src), "r"(sz));
        }
        #pragma unroll
        for (int i = 0; i < NT; i++) {                // B: 32xBN halves
            int idx = t + i * 256;
            int r = idx / (BN / 8);
            int ch = (idx % (BN / 8)) * 8;
            const __half* src = B + (size_t)(k0 + r) * Np + bn + ch;
            uint32_t dst = bs_base[buf] + (uint32_t)((r * LDB + ch) * 2);
            asm volatile("cp.async.cg.shared.global [%0], [%1], 16;"
                         :: "r"(dst), "l"(src));
        }
        asm volatile("cp.async.commit_group;");
    };

    auto compute = [&](int buf) {
        uint32_t a_base = as_base[buf] +
            (uint32_t)(((wm + (lane & 15)) * LDA + (lane >> 4) * 8) * 2);
        uint32_t b_base = bs_base[buf] +
            (uint32_t)(((lane & 15) * LDB + wn) * 2);
        #pragma unroll
        for (int ks = 0; ks < 32; ks += 16) {
            uint32_t a[2][4], bf[4 * NT][2];
            #pragma unroll
            for (int mi = 0; mi < 2; mi++) {
                uint32_t addr = a_base + (uint32_t)((mi * 16 * LDA + ks) * 2);
                asm volatile("ldmatrix.sync.aligned.m8n8.x4.shared.b16 {%0,%1,%2,%3}, [%4];"
                             : "=r"(a[mi][0]), "=r"(a[mi][1]), "=r"(a[mi][2]), "=r"(a[mi][3])
                             : "r"(addr));
            }
            #pragma unroll
            for (int ni = 0; ni < 4 * NT; ni++) {
                uint32_t addr = b_base + (uint32_t)((ks * LDB + ni * 8) * 2);
                asm volatile("ldmatrix.sync.aligned.m8n8.x2.trans.shared.b16 {%0,%1}, [%2];"
                             : "=r"(bf[ni][0]), "=r"(bf[ni][1]) : "r"(addr));
            }
            #pragma unroll
            for (int mi = 0; mi < 2; mi++)
                #pragma unroll
                for (int ni = 0; ni < 4 * NT; ni++) {
                    asm volatile(
                        "mma.sync.aligned.m16n8k16.row.col.f32.f16.f16.f32 "
                        "{%0,%1,%2,%3}, {%4,%5,%6,%7}, {%8,%9}, {%0,%1,%2,%3};"
                        : "+f"(c[mi][ni][0]), "+f"(c[mi][ni][1]),
                          "+f"(c[mi][ni][2]), "+f"(c[mi][ni][3])
                        : "r"(a[mi][0]), "r"(a[mi][1]), "r"(a[mi][2]), "r"(a[mi][3]),
                          "r"(bf[ni][0]), "r"(bf[ni][1]));
                }
        }
    };

    int nIter = Kp >> 5;
    load_tiles(0, 0);
    for (int it = 0; it < nIter; it++) {
        int buf = it & 1;
        if (it + 1 < nIter) {
            load_tiles((it + 1) << 5, buf ^ 1);
            asm volatile("cp.async.wait_group 1;");
        } else {
            asm volatile("cp.async.wait_group 0;");
        }
        __syncthreads();
        compute(buf);
        __syncthreads();
    }

    int r0 = bm + wm + (lane >> 2);
    int col0 = bn + wn + (lane & 3) * 2;
    #pragma unroll
    for (int mi = 0; mi < 2; mi++)
        #pragma unroll
        for (int ni = 0; ni < 4 * NT; ni++)
            #pragma unroll
            for (int hr = 0; hr < 2; hr++) {
                int r = r0 + mi * 16 + hr * 8;
                int col = col0 + ni * 8;
                if (r >= M || col >= padTo) continue;
                float v0 = c[mi][ni][hr * 2 + 0];
                float v1 = c[mi][ni][hr * 2 + 1];
                if (col < N) {
                    if (BIAS) { v0 += bias[col]; v1 += bias[col + 1]; }
                    if (TANH) { v0 = tanhf(v0); v1 = tanhf(v1); }
                } else { v0 = 0.f; v1 = 0.f; }
                if (OUT_HALF) {
                    __half2 p = __floats2half2_rn(v0, v1);
                    *(__half2*)((__half*)Cv + (size_t)r * outStride + col) = p;
                } else {
                    float2 p; p.x = v0; p.y = v1;
                    *(float2*)((float*)Cv + (size_t)r * outStride + col) = p;
                }
            }
}

// ---------------- SpMM: warp per row, fp16 X, fp32 accum, 4-edge unroll -------
// EXACT R4 loop (scalar col/val LDGs — measured local optimum; do not touch).
template<int LANES, bool OUT_FLOAT>
__global__ __launch_bounds__(256)
void spmm_h_kernel(const int* __restrict__ cols, const float* __restrict__ vals,
                   const __half* __restrict__ X, void* __restrict__ Yv) {
    int w = (int)((blockIdx.x * blockDim.x + threadIdx.x) >> 5);
    if (w >= N_NODES) return;
    int lane = threadIdx.x & 31;
    int l = lane < LANES ? lane : 0;
    int e0 = g_rowptr[w], e1 = g_rowptr[w + 1];
    const uint2* __restrict__ X2 = (const uint2*)X;
    float4 acc  = make_float4(0.f, 0.f, 0.f, 0.f);
    float4 acc2 = make_float4(0.f, 0.f, 0.f, 0.f);
    int e = e0;
    for (; e + 4 <= e1; e += 4) {
        int   c0 = __ldg(cols + e),     c1 = __ldg(cols + e + 1);
        int   c2 = __ldg(cols + e + 2), c3 = __ldg(cols + e + 3);
        float v0 = __ldg(vals + e),     v1 = __ldg(vals + e + 1);
        float v2 = __ldg(vals + e + 2), v3 = __ldg(vals + e + 3);
        uint2 p0 = X2[(size_t)c0 * LANES + l];
        uint2 p1 = X2[(size_t)c1 * LANES + l];
        uint2 p2 = X2[(size_t)c2 * LANES + l];
        uint2 p3 = X2[(size_t)c3 * LANES + l];
        float2 a0 = __half22float2(*(const __half2*)&p0.x);
        float2 b0 = __half22float2(*(const __half2*)&p0.y);
        float2 a1 = __half22float2(*(const __half2*)&p1.x);
        float2 b1 = __half22float2(*(const __half2*)&p1.y);
        float2 a2 = __half22float2(*(const __half2*)&p2.x);
        float2 b2 = __half22float2(*(const __half2*)&p2.y);
        float2 a3 = __half22float2(*(const __half2*)&p3.x);
        float2 b3 = __half22float2(*(const __half2*)&p3.y);
        acc.x  = fmaf(v0, a0.x, acc.x);   acc.y  = fmaf(v0, a0.y, acc.y);
        acc.z  = fmaf(v0, b0.x, acc.z);   acc.w  = fmaf(v0, b0.y, acc.w);
        acc2.x = fmaf(v1, a1.x, acc2.x);  acc2.y = fmaf(v1, a1.y, acc2.y);
        acc2.z = fmaf(v1, b1.x, acc2.z);  acc2.w = fmaf(v1, b1.y, acc2.w);
        acc.x  = fmaf(v2, a2.x, acc.x);   acc.y  = fmaf(v2, a2.y, acc.y);
        acc.z  = fmaf(v2, b2.x, acc.z);   acc.w  = fmaf(v2, b2.y, acc.w);
        acc2.x = fmaf(v3, a3.x, acc2.x);  acc2.y = fmaf(v3, a3.y, acc2.y);
        acc2.z = fmaf(v3, b3.x, acc2.z);  acc2.w = fmaf(v3, b3.y, acc2.w);
    }
    for (; e < e1; e++) {
        int   c0 = __ldg(cols + e);
        float v0 = __ldg(vals + e);
        uint2 p0 = X2[(size_t)c0 * LANES + l];
        float2 a0 = __half22float2(*(const __half2*)&p0.x);
        float2 b0 = __half22float2(*(const __half2*)&p0.y);
        acc.x = fmaf(v0, a0.x, acc.x);  acc.y = fmaf(v0, a0.y, acc.y);
        acc.z = fmaf(v0, b0.x, acc.z);  acc.w = fmaf(v0, b0.y, acc.w);
    }
    acc.x += acc2.x; acc.y += acc2.y; acc.z += acc2.z; acc.w += acc2.w;
    if (lane < LANES) {
        if (OUT_FLOAT) {
            float4* Y = (float4*)Yv;
            Y[(size_t)w * LANES + lane] = acc;
        } else {
            __half2 o0 = __floats2half2_rn(acc.x, acc.y);
            __half2 o1 = __floats2half2_rn(acc.z, acc.w);
            uint2 pk;
            pk.x = *(const unsigned*)&o0;
            pk.y = *(const unsigned*)&o1;
            ((uint2*)Yv)[(size_t)w * LANES + lane] = pk;
        }
    }
}

// ------- (+bias) LayerNorm + tanh, warp per row, fp32 in -> fp16 padded out ---
template<int F, int PADF>
__global__ __launch_bounds__(256)
void ln_tanh_kernel(const float* __restrict__ H, const float* __restrict__ pre_bias,
                    const float* __restrict__ g, const float* __restrict__ b,
                    __half* __restrict__ L) {
    int w = (int)((blockIdx.x * blockDim.x + threadIdx.x) >> 5);
    if (w >= N_NODES) return;
    int lane = threadIdx.x & 31;
    const int NI = (F + 31) / 32;
    float v[NI];
    float sum = 0.f;
    #pragma unroll
    for (int i = 0; i < NI; i++) {
        int f = lane + i * 32;
        v[i] = (f < F) ? H[(size_t)w * F + f] + pre_bias[f] : 0.f;
        sum += v[i];
    }
    #pragma unroll
    for (int o = 16; o; o >>= 1) sum += __shfl_xor_sync(0xFFFFFFFFu, sum, o);
    float mean = sum / (float)F;
    float vs = 0.f;
    #pragma unroll
    for (int i = 0; i < NI; i++) {
        int f = lane + i * 32;
        if (f < F) { float d = v[i] - mean; vs += d * d; }
    }
    #pragma unroll
    for (int o = 16; o; o >>= 1) vs += __shfl_xor_sync(0xFFFFFFFFu, vs, o);
    float rstd = rsqrtf(vs / (float)F + EPS);
    const int NO = PADF / 32;
    #pragma unroll
    for (int i = 0; i < NO; i++) {
        int f = lane + i * 32;
        float o = (f < F) ? tanhf((v[i] - mean) * rstd * g[f] + b[f]) : 0.f;
        L[(size_t)w * PADF + f] = __float2half_rn(o);
    }
}

// ---------------- launch ------------------------------------------------------
extern "C" void kernel_launch(void* const* d_in, const int* in_sizes, int n_in,
                              void* d_out, int out_size) {
    const float* x        = (const float*)d_in[0];
    const float* adj_vals = (const float*)d_in[1];
    const float* bn_g     = (const float*)d_in[2];
    const float* bn_b     = (const float*)d_in[3];
    const float* W_in     = (const float*)d_in[4];
    const float* b_in     = (const float*)d_in[5];
    const float* W1       = (const float*)d_in[6];
    const float* b1       = (const float*)d_in[7];
    const float* ln1_g    = (const float*)d_in[8];
    const float* ln1_b    = (const float*)d_in[9];
    const float* W2       = (const float*)d_in[10];
    const float* b2       = (const float*)d_in[11];
    const float* ln2_g    = (const float*)d_in[12];
    const float* ln2_b    = (const float*)d_in[13];
    const float* W_out    = (const float*)d_in[14];
    const float* b_out    = (const float*)d_in[15];
    const int*   adj_rows = (const int*)d_in[16];
    const int*   adj_cols = (const int*)d_in[17];
    float* out = (float*)d_out;

    void *p_xh, *p_h0h, *p_h1h, *p_h2h, *p_l1h, *p_l2h, *p_hf1, *p_hf2;
    void *p_Wph, *p_W1h, *p_W2h, *p_Woh, *p_bp;
    cudaGetSymbolAddress(&p_xh,  g_xh);
    cudaGetSymbolAddress(&p_h0h, g_h0h);
    cudaGetSymbolAddress(&p_h1h, g_h1h);
    cudaGetSymbolAddress(&p_h2h, g_h2h);
    cudaGetSymbolAddress(&p_l1h, g_l1h);
    cudaGetSymbolAddress(&p_l2h, g_l2h);
    cudaGetSymbolAddress(&p_hf1, g_hf1);
    cudaGetSymbolAddress(&p_hf2, g_hf2);
    cudaGetSymbolAddress(&p_Wph, g_Wph);
    cudaGetSymbolAddress(&p_W1h, g_W1h);
    cudaGetSymbolAddress(&p_W2h, g_W2h);
    cudaGetSymbolAddress(&p_Woh, g_Woh);
    cudaGetSymbolAddress(&p_bp,  g_bp);
    __half* xh  = (__half*)p_xh;
    __half* h0h = (__half*)p_h0h;
    __half* h1h = (__half*)p_h1h;
    __half* h2h = (__half*)p_h2h;
    __half* l1h = (__half*)p_l1h;
    __half* l2h = (__half*)p_l2h;
    float*  hf1 = (float*)p_hf1;
    float*  hf2 = (float*)p_hf2;
    __half* Wph = (__half*)p_Wph;
    __half* W1h = (__half*)p_W1h;
    __half* W2h = (__half*)p_W2h;
    __half* Woh = (__half*)p_Woh;
    float*  bp  = (float*)p_bp;

    const int GM = (N_NODES + 127) / 128;
    const int WARP_GRID = (N_NODES * 32 + 255) / 256;

    bn_partial_conv_kernel<<<512, 256>>>(x);
    bn_finalize_kernel<<<1, 256>>>(bn_g, bn_b);
    fold_kernel<<<193, 256>>>(W_in, b_in);

    // h0h = tanh(bn(x) @ W_in + b_in)  [N,140] fp16, stride 160  (NT=1, y=3)
    mma_gemm_kernel<true, true, true, 1><<<dim3(GM, 3), 256>>>(
        xh, Wph, bp, h0h, N_NODES, 140, 256, 192, 160, 160);

    // merged weight convert + CSR rowptr (176 + 391 blocks)
    setup_kernel<<<567, 256>>>(W1, W2, W_out, adj_rows);

    // h1h = h0h @ W1 (bias deferred)  [N,120] fp16, stride 120  (NT=2, short K)
    mma_gemm_kernel<false, false, true, 2><<<dim3(GM, 1), 256>>>(
        h0h, W1h, nullptr, h1h, N_NODES, 120, 160, 128, 120, 120);

    // 4 hops @ F=120; 4th writes fp32 (values ~16^4 exceed fp16 range)
    spmm_h_kernel<30, false><<<WARP_GRID, 256>>>(adj_cols, adj_vals, h1h, h2h);
    spmm_h_kernel<30, false><<<WARP_GRID, 256>>>(adj_cols, adj_vals, h2h, h1h);
    spmm_h_kernel<30, false><<<WARP_GRID, 256>>>(adj_cols, adj_vals, h1h, h2h);
    spmm_h_kernel<30, true ><<<WARP_GRID, 256>>>(adj_cols, adj_vals, h2h, hf1);

    // ln1: fp32 -> fp16 padded [N,128]
    ln_tanh_kernel<120, 128><<<WARP_GRID, 256>>>(hf1, b1, ln1_g, ln1_b, l1h);

    // gemm2 -> [N,100] fp16, stride 100 (into h1h)  (NT=2, short K)
    mma_gemm_kernel<false, false, true, 2><<<dim3(GM, 1), 256>>>(
        l1h, W2h, nullptr, h1h, N_NODES, 100, 128, 128, 100, 100);

    // 4 hops @ F=100; 4th writes fp32
    spmm_h_kernel<25, false><<<WARP_GRID, 256>>>(adj_cols, adj_vals, h1h, h2h);
    spmm_h_kernel<25, false><<<WARP_GRID, 256>>>(adj_cols, adj_vals, h2h, h1h);
    spmm_h_kernel<25, false><<<WARP_GRID, 256>>>(adj_cols, adj_vals, h1h, h2h);
    spmm_h_kernel<25, true ><<<WARP_GRID, 256>>>(adj_cols, adj_vals, h2h, hf2);

    // ln2: fp32 -> fp16 padded [N,128]
    ln_tanh_kernel<100, 128><<<WARP_GRID, 256>>>(hf2, b2, ln2_g, ln2_b, l2h);

    // out = l2 @ W_out + b_out  [N,64] fp32  (NT=1)
    mma_gemm_kernel<true, false, false, 1><<<dim3(GM, 1), 256>>>(
        l2h, Woh, b_out, out, N_NODES, 64, 128, 64, 64, 64);
}